// round 1
// baseline (speedup 1.0000x reference)
#include <cuda_runtime.h>
#include <cstddef>

// ChamferLossSelf: B=4, N=4096, D=3.
// loss[b] = sum_j min_i ||g_i-p_j||^2  + sum_i min_j ||g_i-p_j||^2
//         + ALPHA * sum_k (sort(selfNN(g))[k] - sort(selfNN(p))[k])^2

constexpr int N_PTS  = 4096;
constexpr int QCH    = 128;    // queries per block (= blockDim.x)
constexpr int TILE   = 1024;   // ref points cached in smem per tile
constexpr int MAX_B  = 4;
constexpr float BIG  = 3.4e38f;

// Scratch: per-pass, per-batch NN-min arrays.
// pass 0: query=gts,  ref=preds  (-> loss_2 component)
// pass 1: query=preds, ref=gts   (-> loss_1 component)
// pass 2: query=gts,  ref=gts,  self-excluded
// pass 3: query=preds, ref=preds, self-excluded
__device__ float g_min[4][MAX_B][N_PTS];

__global__ void __launch_bounds__(QCH) nn_kernel(const float* __restrict__ gts,
                                                 const float* __restrict__ preds) {
    const int chunk = blockIdx.x;   // 0..N/QCH-1
    const int pass  = blockIdx.y;   // 0..3
    const int b     = blockIdx.z;

    const float* q;
    const float* r;
    const bool self = (pass >= 2);
    if (pass == 0)      { q = gts;   r = preds; }
    else if (pass == 1) { q = preds; r = gts;   }
    else if (pass == 2) { q = gts;   r = gts;   }
    else                { q = preds; r = preds; }
    q += (size_t)b * N_PTS * 3;
    r += (size_t)b * N_PTS * 3;

    const int qi = chunk * QCH + threadIdx.x;
    const float qx = q[qi * 3 + 0];
    const float qy = q[qi * 3 + 1];
    const float qz = q[qi * 3 + 2];

    float best = BIG;

    __shared__ float4 sref[TILE];

    for (int tile = 0; tile < N_PTS; tile += TILE) {
        __syncthreads();
        // Stage TILE ref points into smem (float4 -> single LDS.128 broadcast in compute loop)
        for (int t = threadIdx.x; t < TILE; t += QCH) {
            const float* p = r + (size_t)(tile + t) * 3;
            sref[t] = make_float4(p[0], p[1], p[2], 0.0f);
        }
        __syncthreads();

        if (!self) {
#pragma unroll 8
            for (int t = 0; t < TILE; ++t) {
                float4 rp = sref[t];
                float dx = qx - rp.x;
                float dy = qy - rp.y;
                float dz = qz - rp.z;
                float d  = fmaf(dz, dz, fmaf(dy, dy, dx * dx));
                best = fminf(best, d);
            }
        } else {
            const int rel = qi - tile;   // index of the diagonal element in this tile
#pragma unroll 8
            for (int t = 0; t < TILE; ++t) {
                float4 rp = sref[t];
                float dx = qx - rp.x;
                float dy = qy - rp.y;
                float dz = qz - rp.z;
                float d  = fmaf(dz, dz, fmaf(dy, dy, dx * dx));
                d = (t == rel) ? BIG : d;   // diagonal masked (DIAG_FILL never wins)
                best = fminf(best, d);
            }
        }
    }

    g_min[pass][b][qi] = best;
}

// One block per batch: bitonic-sort the two self-NN arrays in smem, then fused
// reduction of loss1 + loss2 + ordering term.
__global__ void __launch_bounds__(1024) finalize_kernel(float* __restrict__ out) {
    const int b   = blockIdx.x;
    const int tid = threadIdx.x;

    __shared__ float s1[N_PTS];
    __shared__ float s2[N_PTS];

    for (int i = tid; i < N_PTS; i += 1024) {
        s1[i] = g_min[2][b][i];
        s2[i] = g_min[3][b][i];
    }

    // Bitonic sort (ascending) on both arrays simultaneously.
    for (int k = 2; k <= N_PTS; k <<= 1) {
        for (int j = k >> 1; j > 0; j >>= 1) {
            __syncthreads();
            for (int i = tid; i < N_PTS; i += 1024) {
                const int ix = i ^ j;
                if (ix > i) {
                    const bool up = ((i & k) == 0);
                    float a = s1[i], bb = s1[ix];
                    if ((a > bb) == up) { s1[i] = bb; s1[ix] = a; }
                    float c = s2[i], dd = s2[ix];
                    if ((c > dd) == up) { s2[i] = dd; s2[ix] = c; }
                }
            }
        }
    }
    __syncthreads();

    // Fused reduction: ordering term + cross-term sums (ALPHA = 1).
    float local = 0.0f;
    for (int i = tid; i < N_PTS; i += 1024) {
        const float diff = s1[i] - s2[i];
        local = fmaf(diff, diff, local);
        local += g_min[0][b][i] + g_min[1][b][i];
    }
    __syncthreads();          // everyone done reading s1 before reuse
    s1[tid] = local;
    __syncthreads();
    for (int s = 512; s > 0; s >>= 1) {
        if (tid < s) s1[tid] += s1[tid + s];
        __syncthreads();
    }
    if (tid == 0) out[b] = s1[0];
}

extern "C" void kernel_launch(void* const* d_in, const int* in_sizes, int n_in,
                              void* d_out, int out_size) {
    const float* gts   = (const float*)d_in[0];
    const float* preds = (const float*)d_in[1];
    float* out = (float*)d_out;

    const int B = in_sizes[0] / (N_PTS * 3);

    dim3 grid(N_PTS / QCH, 4, B);
    nn_kernel<<<grid, QCH>>>(gts, preds);
    finalize_kernel<<<B, 1024>>>(out);
}

// round 2
// speedup vs baseline: 1.8425x; 1.8425x over previous
#include <cuda_runtime.h>
#include <cstddef>

// ChamferLossSelf: B=4, N=4096, D=3.
// loss[b] = sum_j min_i ||g_i-p_j||^2 + sum_i min_j ||g_i-p_j||^2
//         + sum_k (sort(selfNN(g))[k] - sort(selfNN(p))[k])^2
//
// Key identity: min_r ||q-r||^2 = |q|^2 + min_r (|r|^2 - 2 q.r)
// -> inner loop is 3 FFMA + 1 FMNMX + 1 LDS.128 per distance (fma-pipe bound).

constexpr int N_PTS = 4096;
constexpr int B_MAX = 4;
constexpr int QB    = 256;    // threads per block == queries per block
constexpr int TILE  = 1024;   // ref points staged in smem
constexpr float BIG = 3.4e38f;

__device__ float g_selfmin[2][B_MAX][N_PTS];           // self-NN sq dists (gts, preds)
__device__ float g_sorted [2][B_MAX][N_PTS];           // sorted self-NN dists
__device__ float g_partial[2][B_MAX][N_PTS / QB];      // cross-NN partial sums

// ---------------------------------------------------------------------------
// K1: self-NN passes. pass 0: gts vs gts, pass 1: preds vs preds.
// grid (N/QB, 2, B), 256 threads.
// ---------------------------------------------------------------------------
__global__ void __launch_bounds__(QB) self_nn_kernel(const float* __restrict__ gts,
                                                     const float* __restrict__ preds) {
    const int chunk = blockIdx.x;
    const int pass  = blockIdx.y;
    const int b     = blockIdx.z;
    const float* p = (pass == 0 ? gts : preds) + (size_t)b * N_PTS * 3;

    const int qi = chunk * QB + threadIdx.x;
    const float qx = p[qi * 3 + 0];
    const float qy = p[qi * 3 + 1];
    const float qz = p[qi * 3 + 2];
    const float qq = fmaf(qx, qx, fmaf(qy, qy, qz * qz));
    const float nx = -2.0f * qx, ny = -2.0f * qy, nz = -2.0f * qz;

    __shared__ float4 sref[TILE];
    float best0 = BIG, best1 = BIG;
    const int diag_tile = (chunk * QB) & ~(TILE - 1);   // tile holding this block's diagonals

    for (int t0 = 0; t0 < N_PTS; t0 += TILE) {
        __syncthreads();
#pragma unroll
        for (int t = threadIdx.x; t < TILE; t += QB) {
            const float* rp = p + (size_t)(t0 + t) * 3;
            const float rx = rp[0], ry = rp[1], rz = rp[2];
            sref[t] = make_float4(rx, ry, rz, fmaf(rx, rx, fmaf(ry, ry, rz * rz)));
        }
        __syncthreads();

        if (t0 == diag_tile) {
            const int rel = qi - t0;
#pragma unroll 8
            for (int t = 0; t < TILE; t += 2) {
                float4 r0 = sref[t], r1 = sref[t + 1];
                float d0 = fmaf(nx, r0.x, fmaf(ny, r0.y, fmaf(nz, r0.z, r0.w)));
                float d1 = fmaf(nx, r1.x, fmaf(ny, r1.y, fmaf(nz, r1.z, r1.w)));
                if (t == rel)     d0 = BIG;
                if (t + 1 == rel) d1 = BIG;
                best0 = fminf(best0, d0);
                best1 = fminf(best1, d1);
            }
        } else {
#pragma unroll 8
            for (int t = 0; t < TILE; t += 2) {
                float4 r0 = sref[t], r1 = sref[t + 1];
                float d0 = fmaf(nx, r0.x, fmaf(ny, r0.y, fmaf(nz, r0.z, r0.w)));
                float d1 = fmaf(nx, r1.x, fmaf(ny, r1.y, fmaf(nz, r1.z, r1.w)));
                best0 = fminf(best0, d0);
                best1 = fminf(best1, d1);
            }
        }
    }
    g_selfmin[pass][b][qi] = fminf(best0, best1) + qq;
}

// ---------------------------------------------------------------------------
// Hybrid bitonic sort of 4096 floats in smem, 256 threads.
// j >= 32 stages via smem; j <= 16 stages via warp shuffles in registers.
// ---------------------------------------------------------------------------
__device__ __forceinline__ void bitonic_sort_4096(float* s) {
    const int t = threadIdx.x;
    float v[16];

    // k = 2..32 : entirely register/shuffle stages
#pragma unroll
    for (int w = 0; w < 16; ++w) v[w] = s[w * 256 + t];
#pragma unroll
    for (int k = 2; k <= 32; k <<= 1) {
#pragma unroll
        for (int j = k >> 1; j >= 1; j >>= 1) {
#pragma unroll
            for (int w = 0; w < 16; ++w) {
                const int i = w * 256 + t;
                const float pv = __shfl_xor_sync(0xffffffffu, v[w], j);
                const bool up    = ((i & k) == 0);
                const bool lower = ((t & j) == 0);
                v[w] = (lower == up) ? fminf(v[w], pv) : fmaxf(v[w], pv);
            }
        }
    }
#pragma unroll
    for (int w = 0; w < 16; ++w) s[w * 256 + t] = v[w];

    // k = 64..4096 : smem stages down to j=32, then register stages j=16..1
    for (int k = 64; k <= 4096; k <<= 1) {
        for (int j = k >> 1; j >= 32; j >>= 1) {
            __syncthreads();
#pragma unroll
            for (int w = 0; w < 16; ++w) {
                const int i = w * 256 + t;
                if ((i & j) == 0) {
                    const int ix = i | j;
                    const float a = s[i], c = s[ix];
                    const bool up = ((i & k) == 0);
                    if ((a > c) == up) { s[i] = c; s[ix] = a; }
                }
            }
        }
        __syncthreads();
#pragma unroll
        for (int w = 0; w < 16; ++w) v[w] = s[w * 256 + t];
#pragma unroll
        for (int j = 16; j >= 1; j >>= 1) {
#pragma unroll
            for (int w = 0; w < 16; ++w) {
                const int i = w * 256 + t;
                const float pv = __shfl_xor_sync(0xffffffffu, v[w], j);
                const bool up    = ((i & k) == 0);
                const bool lower = ((t & j) == 0);
                v[w] = (lower == up) ? fminf(v[w], pv) : fmaxf(v[w], pv);
            }
        }
#pragma unroll
        for (int w = 0; w < 16; ++w) s[w * 256 + t] = v[w];
    }
    __syncthreads();
}

// ---------------------------------------------------------------------------
// K2 (fused): blocks [0, 2B) sort one self-NN array each (hidden under cross);
// blocks [2B, 2B + 32B) do cross-NN with in-block sum reduction.
// 1D grid, 256 threads.
// ---------------------------------------------------------------------------
__global__ void __launch_bounds__(QB) fused_kernel(const float* __restrict__ gts,
                                                   const float* __restrict__ preds,
                                                   int B) {
    __shared__ float4 smem4[TILE];   // 16 KB, shared by both roles

    if ((int)blockIdx.x < 2 * B) {
        // ---- sort role ----
        const int arr = blockIdx.x & 1;
        const int b   = blockIdx.x >> 1;
        float* s = (float*)smem4;
        for (int i = threadIdx.x; i < N_PTS; i += QB) s[i] = g_selfmin[arr][b][i];
        __syncthreads();
        bitonic_sort_4096(s);
        for (int i = threadIdx.x; i < N_PTS; i += QB) g_sorted[arr][b][i] = s[i];
        return;
    }

    // ---- cross-NN role ----
    const int idx   = blockIdx.x - 2 * B;
    const int chunk = idx & (N_PTS / QB - 1);
    const int pass  = (idx / (N_PTS / QB)) & 1;
    const int b     = idx / (2 * (N_PTS / QB));
    // pass 0: query = gts, ref = preds ; pass 1: query = preds, ref = gts
    const float* q = (pass == 0 ? gts : preds) + (size_t)b * N_PTS * 3;
    const float* r = (pass == 0 ? preds : gts) + (size_t)b * N_PTS * 3;

    const int qi = chunk * QB + threadIdx.x;
    const float qx = q[qi * 3 + 0];
    const float qy = q[qi * 3 + 1];
    const float qz = q[qi * 3 + 2];
    const float qq = fmaf(qx, qx, fmaf(qy, qy, qz * qz));
    const float nx = -2.0f * qx, ny = -2.0f * qy, nz = -2.0f * qz;

    float best0 = BIG, best1 = BIG;
    for (int t0 = 0; t0 < N_PTS; t0 += TILE) {
        __syncthreads();
#pragma unroll
        for (int t = threadIdx.x; t < TILE; t += QB) {
            const float* rp = r + (size_t)(t0 + t) * 3;
            const float rx = rp[0], ry = rp[1], rz = rp[2];
            smem4[t] = make_float4(rx, ry, rz, fmaf(rx, rx, fmaf(ry, ry, rz * rz)));
        }
        __syncthreads();
#pragma unroll 8
        for (int t = 0; t < TILE; t += 2) {
            float4 r0 = smem4[t], r1 = smem4[t + 1];
            float d0 = fmaf(nx, r0.x, fmaf(ny, r0.y, fmaf(nz, r0.z, r0.w)));
            float d1 = fmaf(nx, r1.x, fmaf(ny, r1.y, fmaf(nz, r1.z, r1.w)));
            best0 = fminf(best0, d0);
            best1 = fminf(best1, d1);
        }
    }
    float val = fminf(best0, best1) + qq;

    // block sum reduction (deterministic)
    __shared__ float red[QB / 32];
#pragma unroll
    for (int o = 16; o; o >>= 1) val += __shfl_xor_sync(0xffffffffu, val, o);
    if ((threadIdx.x & 31) == 0) red[threadIdx.x >> 5] = val;
    __syncthreads();
    if (threadIdx.x == 0) {
        float sum = 0.0f;
#pragma unroll
        for (int w = 0; w < QB / 32; ++w) sum += red[w];
        g_partial[pass][b][chunk] = sum;
    }
}

// ---------------------------------------------------------------------------
// K3: combine. grid = B, 256 threads.
// ---------------------------------------------------------------------------
__global__ void __launch_bounds__(QB) combine_kernel(float* __restrict__ out) {
    const int b = blockIdx.x;
    const int t = threadIdx.x;
    float acc = 0.0f;
    for (int i = t; i < N_PTS; i += QB) {
        const float d = g_sorted[0][b][i] - g_sorted[1][b][i];
        acc = fmaf(d, d, acc);
    }
    if (t < 2 * (N_PTS / QB))   // fold in the 32 cross partial sums
        acc += g_partial[t / (N_PTS / QB)][b][t & (N_PTS / QB - 1)];

    __shared__ float red[QB / 32];
#pragma unroll
    for (int o = 16; o; o >>= 1) acc += __shfl_xor_sync(0xffffffffu, acc, o);
    if ((t & 31) == 0) red[t >> 5] = acc;
    __syncthreads();
    if (t == 0) {
        float sum = 0.0f;
#pragma unroll
        for (int w = 0; w < QB / 32; ++w) sum += red[w];
        out[b] = sum;
    }
}

extern "C" void kernel_launch(void* const* d_in, const int* in_sizes, int n_in,
                              void* d_out, int out_size) {
    const float* gts   = (const float*)d_in[0];
    const float* preds = (const float*)d_in[1];
    float* out = (float*)d_out;
    const int B = in_sizes[0] / (N_PTS * 3);

    dim3 g1(N_PTS / QB, 2, B);
    self_nn_kernel<<<g1, QB>>>(gts, preds);

    const int n_fused = 2 * B + 2 * B * (N_PTS / QB);   // 8 sort + 128 cross for B=4
    fused_kernel<<<n_fused, QB>>>(gts, preds, B);

    combine_kernel<<<B, QB>>>(out);
}